// round 16
// baseline (speedup 1.0000x reference)
#include <cuda_runtime.h>
#include <cstddef>

// Problem constants
#define N_NODES 2048
#define K_EDGE  8
#define FN_FEAT 16
#define O_OUT   32
#define NK      (N_NODES * K_EDGE)       // 16384
#define NK4     (NK / 4)                 // 4096
#define SEGS    32
#define SEG_LEN (N_NODES / SEGS)         // 64

// Scratch (device globals; no allocation allowed)
__device__ float g_rinv[N_NODES];
__device__ float g_part[SEGS * NK];          // partial agg_e, [seg][j*K+k]  (2 MB)
__device__ float g_colpart[SEGS * N_NODES];  // partial col_sum, [seg][j]

// ---------------------------------------------------------------------------
// Kernel 1: row sums of adj -> r_inv. One block (128 thr) per row.
// Each thread: 4 independent float4 loads -> high MLP, 55 warps/SM.
// ---------------------------------------------------------------------------
__global__ __launch_bounds__(128) void rowsum_kernel(const float* __restrict__ adj) {
    __shared__ float s_red[4];
    int row  = blockIdx.x;
    int tid  = threadIdx.x;
    int lane = tid & 31;
    int wid  = tid >> 5;

    const float4* row4 = reinterpret_cast<const float4*>(adj + (size_t)row * N_NODES);
    // 512 float4 per row, 128 threads -> 4 each (independent)
    float4 v0 = __ldg(row4 + tid);
    float4 v1 = __ldg(row4 + tid + 128);
    float4 v2 = __ldg(row4 + tid + 256);
    float4 v3 = __ldg(row4 + tid + 384);

    float s = ((v0.x + v0.y) + (v0.z + v0.w))
            + ((v1.x + v1.y) + (v1.z + v1.w))
            + ((v2.x + v2.y) + (v2.z + v2.w))
            + ((v3.x + v3.y) + (v3.z + v3.w));

    #pragma unroll
    for (int off = 16; off > 0; off >>= 1)
        s += __shfl_xor_sync(0xFFFFFFFFu, s, off);
    if (lane == 0) s_red[wid] = s;
    __syncthreads();

    if (tid == 0) {
        float tot = s_red[0] + s_red[1] + s_red[2] + s_red[3];
        float r = 1.0f / tot;
        if (!isfinite(r)) r = 0.0f;
        g_rinv[row] = r;
    }
}

// ---------------------------------------------------------------------------
// Kernel 2: streaming pass over the edge tensor.
//   grid = (NK4/256 = 16, SEGS = 32), block = 256.
// Thread handles one float4 of (j,k) space (4 consecutive k-slots), loops
// over its 64-row i-segment. Edge loads: LDG.128, fully coalesced.
// ---------------------------------------------------------------------------
__global__ __launch_bounds__(256) void agg_kernel(
    const float* __restrict__ edge, const float* __restrict__ adj)
{
    __shared__ float s_a[SEG_LEN];   // r_inv over this segment

    int tid = threadIdx.x;
    int t4  = blockIdx.x * 256 + tid;     // 0..4095 (float4 index in (j,k))
    int j   = t4 >> 1;                    // 2 threads per j (k 0-3 / 4-7)
    int i0  = blockIdx.y * SEG_LEN;

    if (tid < SEG_LEN) s_a[tid] = g_rinv[i0 + tid];
    __syncthreads();

    const float4* ep = reinterpret_cast<const float4*>(edge) + (size_t)i0 * NK4 + t4;
    const float*  ap = adj + (size_t)i0 * N_NODES + j;

    float ax = 0.f, ay = 0.f, az = 0.f, aw = 0.f;
    float cs = 0.f;

    #pragma unroll 8
    for (int ii = 0; ii < SEG_LEN; ii++) {
        float  a = s_a[ii] * __ldg(ap + (size_t)ii * N_NODES);
        float4 e = __ldg(ep + (size_t)ii * NK4);
        ax = fmaf(a, e.x, ax);
        ay = fmaf(a, e.y, ay);
        az = fmaf(a, e.z, az);
        aw = fmaf(a, e.w, aw);
        cs += a;
    }

    float4 acc = make_float4(ax, ay, az, aw);
    reinterpret_cast<float4*>(g_part)[(size_t)blockIdx.y * NK4 + t4] = acc;
    if ((t4 & 1) == 0)
        g_colpart[blockIdx.y * N_NODES + j] = cs;
}

// ---------------------------------------------------------------------------
// Kernel 3: epilogue. One block per 32-j tile.
//   Phase A: each thread reduces one (j,k) over SEGS partials (coalesced,
//            L2-resident); k==0 threads also reduce col_sum.
//   Phase B: 1024 outputs per tile, 4 per thread, from shared.
// ---------------------------------------------------------------------------
__global__ __launch_bounds__(256) void epilogue_kernel(
    const float* __restrict__ nf, const float* __restrict__ w,
    float* __restrict__ out)
{
    __shared__ float sw[(K_EDGE + FN_FEAT) * O_OUT];  // 768
    __shared__ float s_agg[256];                      // 32 j x 8 k
    __shared__ float s_cs[32];
    __shared__ float s_nf[32 * FN_FEAT];              // 512

    int tid = threadIdx.x;
    int jt  = blockIdx.x;            // 0..63, tile covers j in [jt*32, jt*32+32)
    int t   = jt * 256 + tid;        // global (j,k) slot

    #pragma unroll
    for (int x = tid; x < (K_EDGE + FN_FEAT) * O_OUT; x += 256) sw[x] = w[x];
    #pragma unroll
    for (int x = tid; x < 32 * FN_FEAT; x += 256) s_nf[x] = nf[jt * (32 * FN_FEAT) + x];

    float s = 0.f;
    #pragma unroll
    for (int seg = 0; seg < SEGS; seg++)
        s += g_part[(size_t)seg * NK + t];
    s_agg[tid] = s;

    if ((tid & 7) == 0) {
        int j = t >> 3;
        float c = 0.f;
        #pragma unroll
        for (int seg = 0; seg < SEGS; seg++)
            c += g_colpart[seg * N_NODES + j];
        s_cs[tid >> 3] = c;
    }
    __syncthreads();

    #pragma unroll
    for (int q = 0; q < 4; q++) {
        int u  = q * 256 + tid;      // 0..1023
        int jl = u >> 5;             // 0..31
        int o  = u & 31;

        float v = 0.f;
        #pragma unroll
        for (int k = 0; k < K_EDGE; k++)
            v = fmaf(s_agg[jl * K_EDGE + k], sw[k * O_OUT + o], v);

        float v2 = 0.f;
        #pragma unroll
        for (int f = 0; f < FN_FEAT; f++)
            v2 = fmaf(s_nf[jl * FN_FEAT + f], sw[(K_EDGE + f) * O_OUT + o], v2);

        out[(size_t)(jt * 32 + jl) * O_OUT + o] = fmaf(s_cs[jl], v2, v);
    }
}

// ---------------------------------------------------------------------------
extern "C" void kernel_launch(void* const* d_in, const int* in_sizes, int n_in,
                              void* d_out, int out_size)
{
    const float* node_features = (const float*)d_in[0]; // (N, FN)
    const float* edge_feat     = (const float*)d_in[1]; // (N, N, K)
    const float* adj           = (const float*)d_in[2]; // (N, N)
    const float* weight        = (const float*)d_in[3]; // (K+FN, O)
    float* out = (float*)d_out;                         // (N, O)

    rowsum_kernel<<<N_NODES, 128>>>(adj);

    dim3 g2(NK4 / 256, SEGS);
    agg_kernel<<<g2, 256>>>(edge_feat, adj);

    epilogue_kernel<<<NK / 256, 256>>>(node_features, weight, out);
}

// round 17
// speedup vs baseline: 1.1144x; 1.1144x over previous
#include <cuda_runtime.h>
#include <cstddef>

// Problem constants
#define N_NODES 2048
#define K_EDGE  8
#define FN_FEAT 16
#define O_OUT   32
#define NK      (N_NODES * K_EDGE)       // 16384
#define NK4     (NK / 4)                 // 4096
#define SEGS    32
#define SEG_LEN (N_NODES / SEGS)         // 64
#define NCTA    512
#define NTHR    256

// Scratch (device globals; no allocation allowed)
__device__ float g_rinv[N_NODES];
__device__ float g_part[SEGS * NK];          // partial agg_e (2 MB)
__device__ float g_colpart[SEGS * N_NODES];  // partial col_sum
__device__ unsigned g_bar[2];                // grid-barrier tickets (monotonic)

// Ticket/epoch grid barrier: no reset needed across graph replays.
// Each launch adds exactly NCTA tickets per barrier slot; a CTA's release
// goal is its own ticket rounded up to the next multiple of NCTA.
__device__ __forceinline__ void grid_barrier(int slot) {
    __syncthreads();
    if (threadIdx.x == 0) {
        __threadfence();                                  // publish our writes
        unsigned ticket = atomicAdd(&g_bar[slot], 1u) + 1u;
        unsigned goal   = (ticket + (NCTA - 1u)) & ~(NCTA - 1u);
        while (*((volatile unsigned*)&g_bar[slot]) < goal) { }
        __threadfence();
    }
    __syncthreads();
}

__global__ __launch_bounds__(NTHR, 4) void fused_kernel(
    const float* __restrict__ nf,    // (N, FN)
    const float* __restrict__ edge,  // (N, N, K)
    const float* __restrict__ adj,   // (N, N)
    const float* __restrict__ w,     // (K+FN, O)
    float* __restrict__ out)         // (N, O)
{
    __shared__ float s_red[32];                        // phase 1: 4 rows x 8 warps
    __shared__ float s_a[SEG_LEN];                     // phase 2
    __shared__ float sw[(K_EDGE + FN_FEAT) * O_OUT];   // phase 3: 768
    __shared__ float s_agg[256];
    __shared__ float s_cs[32];
    __shared__ float s_nf[32 * FN_FEAT];

    const int tid  = threadIdx.x;
    const int bx   = blockIdx.x;
    const int lane = tid & 31;
    const int wid  = tid >> 5;

    // ------------------------------------------------------------------
    // Phase 1: row sums -> g_rinv.  4 rows per CTA, full-chip streaming.
    // ------------------------------------------------------------------
    {
        const float4* base = reinterpret_cast<const float4*>(adj)
                           + (size_t)(bx * 4) * (N_NODES / 4);
        float part[4];
        #pragma unroll
        for (int r = 0; r < 4; r++) {
            float4 a = __ldcs(base + (size_t)r * (N_NODES / 4) + tid);
            float4 b = __ldcs(base + (size_t)r * (N_NODES / 4) + tid + 256);
            part[r] = ((a.x + a.y) + (a.z + a.w)) + ((b.x + b.y) + (b.z + b.w));
        }
        #pragma unroll
        for (int r = 0; r < 4; r++) {
            float s = part[r];
            #pragma unroll
            for (int off = 16; off > 0; off >>= 1)
                s += __shfl_xor_sync(0xFFFFFFFFu, s, off);
            if (lane == 0) s_red[r * 8 + wid] = s;
        }
        __syncthreads();
        if (tid < 4) {
            float tot = 0.f;
            #pragma unroll
            for (int q = 0; q < 8; q++) tot += s_red[tid * 8 + q];
            float r = 1.0f / tot;
            if (!isfinite(r)) r = 0.0f;
            g_rinv[bx * 4 + tid] = r;
        }
    }

    grid_barrier(0);

    // ------------------------------------------------------------------
    // Phase 2: streaming agg over the edge tensor.
    //   bx -> (jtile = bx & 15, seg = bx >> 4)
    // ------------------------------------------------------------------
    {
        const int jtile = bx & 15;
        const int seg   = bx >> 4;
        const int t4    = jtile * 256 + tid;   // float4 index in (j,k) space
        const int j     = t4 >> 1;
        const int i0    = seg * SEG_LEN;

        if (tid < SEG_LEN) s_a[tid] = __ldcg(&g_rinv[i0 + tid]);
        __syncthreads();

        const float4* ep = reinterpret_cast<const float4*>(edge)
                         + (size_t)i0 * NK4 + t4;
        const float*  ap = adj + (size_t)i0 * N_NODES + j;

        float ax = 0.f, ay = 0.f, az = 0.f, aw = 0.f, cs = 0.f;

        #pragma unroll 4
        for (int ii = 0; ii < SEG_LEN; ii++) {
            float  a = s_a[ii] * __ldcs(ap + (size_t)ii * N_NODES);
            float4 e = __ldcs(ep + (size_t)ii * NK4);
            ax = fmaf(a, e.x, ax);
            ay = fmaf(a, e.y, ay);
            az = fmaf(a, e.z, az);
            aw = fmaf(a, e.w, aw);
            cs += a;
        }

        reinterpret_cast<float4*>(g_part)[(size_t)seg * NK4 + t4]
            = make_float4(ax, ay, az, aw);
        if ((t4 & 1) == 0)
            g_colpart[seg * N_NODES + j] = cs;
    }

    grid_barrier(1);

    // ------------------------------------------------------------------
    // Phase 3: epilogue on CTAs 0..63 (32 j's per CTA).
    // ------------------------------------------------------------------
    if (bx >= 64) return;
    {
        const int jt = bx;
        const int t  = jt * 256 + tid;        // global (j,k) slot

        #pragma unroll
        for (int x = tid; x < (K_EDGE + FN_FEAT) * O_OUT; x += 256) sw[x] = w[x];
        #pragma unroll
        for (int x = tid; x < 32 * FN_FEAT; x += 256)
            s_nf[x] = nf[jt * (32 * FN_FEAT) + x];

        float s = 0.f;
        #pragma unroll
        for (int seg = 0; seg < SEGS; seg++)
            s += __ldcg(&g_part[(size_t)seg * NK + t]);
        s_agg[tid] = s;

        if ((tid & 7) == 0) {
            int j = t >> 3;
            float c = 0.f;
            #pragma unroll
            for (int seg = 0; seg < SEGS; seg++)
                c += __ldcg(&g_colpart[seg * N_NODES + j]);
            s_cs[tid >> 3] = c;
        }
        __syncthreads();

        #pragma unroll
        for (int q = 0; q < 4; q++) {
            int u  = q * 256 + tid;
            int jl = u >> 5;
            int o  = u & 31;

            float v = 0.f;
            #pragma unroll
            for (int k = 0; k < K_EDGE; k++)
                v = fmaf(s_agg[jl * K_EDGE + k], sw[k * O_OUT + o], v);

            float v2 = 0.f;
            #pragma unroll
            for (int f = 0; f < FN_FEAT; f++)
                v2 = fmaf(s_nf[jl * FN_FEAT + f], sw[(K_EDGE + f) * O_OUT + o], v2);

            out[(size_t)(jt * 32 + jl) * O_OUT + o] = fmaf(s_cs[jl], v2, v);
        }
    }
}

// ---------------------------------------------------------------------------
extern "C" void kernel_launch(void* const* d_in, const int* in_sizes, int n_in,
                              void* d_out, int out_size)
{
    const float* node_features = (const float*)d_in[0]; // (N, FN)
    const float* edge_feat     = (const float*)d_in[1]; // (N, N, K)
    const float* adj           = (const float*)d_in[2]; // (N, N)
    const float* weight        = (const float*)d_in[3]; // (K+FN, O)
    float* out = (float*)d_out;                         // (N, O)

    fused_kernel<<<NCTA, NTHR>>>(node_features, edge_feat, adj, weight, out);
}